// round 12
// baseline (speedup 1.0000x reference)
#include <cuda_runtime.h>
#include <cuda_fp16.h>
#include <cooperative_groups.h>
#include <cstdint>

namespace cg = cooperative_groups;

#define NN   100000
#define EE   3200000
#define INC  128
#define HID  64
#define OUTC 16

// ---------------- scratch (static device globals; no allocation) -------------
__device__ __half2 g_h0h[NN * 32];    // x @ W1, fp16 UNSCALED, 64ch
__device__ __half2 g_zh[NN * 16];     // relu-projected layer, fp16 UNSCALED, 32ch
__device__ float g_dis[NN];           // (deg+1)^-1/2
__device__ int   g_csr[EE];           // src indices sorted by dst
__device__ int   g_degi[NN];          // zero at entry (load-init + tail re-zero)
__device__ int   g_off[NN + 1];       // CSR row ptr, off[n] = E sentinel
__device__ int   g_woff[NN];
__device__ int   g_bsum[1024];
__device__ int   g_bpre[1024];

// ---------------- stream/event resources (created at load, before checkpoint)-
namespace {
struct Resources {
    cudaStream_t s2;
    cudaEvent_t  ev_fork, ev_join;
    Resources() {
        cudaStreamCreateWithFlags(&s2, cudaStreamNonBlocking);
        cudaEventCreateWithFlags(&ev_fork, cudaEventDisableTiming);
        cudaEventCreateWithFlags(&ev_join, cudaEventDisableTiming);
    }
};
Resources g_res;
}

// warp-uniform dtype detection: int64 edge data has all-zero odd 32-bit words
__device__ __forceinline__ bool detect64(const int* e32) {
    return ((e32[1] | e32[3] | e32[5] | e32[7] | e32[9]) == 0);
}

// ---------------- kernel 2: degree count (self-detecting) --------------------
__global__ void k_conv_count(const void* eidx, int E) {
    int i = blockIdx.x * blockDim.x + threadIdx.x;
    if (i >= E) return;
    const int* e32 = (const int*)eidx;
    int v;
    if (detect64(e32)) v = (int)((const long long*)eidx)[E + i];
    else               v = e32[E + i];
    atomicAdd(&g_degi[v], 1);
}

// ---------------- kernel 3: cooperative scan + dis + scatter -----------------
__global__ __launch_bounds__(256, 4) void k_coop(const void* eidx, int n, int E, int nb) {
    cg::grid_group grid = cg::this_grid();
    __shared__ int s[256];
    int tid  = threadIdx.x;
    int gtid = blockIdx.x * 256 + tid;

    // phase 1: per-block inclusive scan of degrees
    int v = 0, lex = 0;
    if (blockIdx.x < (unsigned)nb) {
        v = (gtid < n) ? g_degi[gtid] : 0;
        s[tid] = v;
        __syncthreads();
        #pragma unroll
        for (int off = 1; off < 256; off <<= 1) {
            int t = (tid >= off) ? s[tid - off] : 0;
            __syncthreads();
            s[tid] += t;
            __syncthreads();
        }
        lex = s[tid] - v;
        if (tid == 255) g_bsum[blockIdx.x] = s[255];
    }
    grid.sync();

    // phase 2: scan of block sums (one warp, 13 partials per lane)
    if (blockIdx.x == 0 && tid < 32) {
        const int CH = 13;                       // 32*13 = 416 >= nb
        int loc[CH];
        int sum = 0;
        #pragma unroll
        for (int j = 0; j < CH; j++) {
            int idx = tid * CH + j;
            loc[j] = sum;                        // lane-local exclusive
            sum += (idx < nb) ? g_bsum[idx] : 0;
        }
        // warp exclusive scan of lane sums
        int excl = 0;
        #pragma unroll
        for (int off = 1; off < 32; off <<= 1) {
            int t = __shfl_up_sync(0xffffffffu, sum, off);
            if (tid >= off) sum += t;
        }
        excl = __shfl_up_sync(0xffffffffu, sum, 1);
        if (tid == 0) excl = 0;
        #pragma unroll
        for (int j = 0; j < CH; j++) {
            int idx = tid * CH + j;
            if (idx < nb) g_bpre[idx] = excl + loc[j];
        }
    }
    grid.sync();

    // phase 3: finalize row pointers, dis, sentinel, re-zero degi
    if (blockIdx.x < (unsigned)nb && gtid < n) {
        int o = lex + g_bpre[blockIdx.x];
        g_off[gtid]  = o;
        g_woff[gtid] = o;
        g_dis[gtid]  = rsqrtf((float)(v + 1));
        g_degi[gtid] = 0;                        // invariant for next launch
    }
    if (gtid == 0) g_off[n] = E;
    grid.sync();

    // phase 4: counting-sort scatter (self-detecting, converts src inline)
    const int* e32 = (const int*)eidx;
    int nth = gridDim.x * 256;
    if (detect64(e32)) {
        const long long* e64 = (const long long*)eidx;
        for (int e = gtid; e < E; e += nth) {
            int d = (int)e64[E + e];
            int pos = atomicAdd(&g_woff[d], 1);
            g_csr[pos] = (int)e64[e];
        }
    } else {
        for (int e = gtid; e < E; e += nth) {
            int d = e32[E + e];
            int pos = atomicAdd(&g_woff[d], 1);
            g_csr[pos] = e32[e];
        }
    }
}

// ---------------- kernel 1: GEMM1 -> unscaled fp16 (runs at t=0 on s2) -------
__global__ __launch_bounds__(256) void k_gemm1f(const float* __restrict__ x,
                                                const float* __restrict__ W,
                                                int n) {
    __shared__ float Ws[INC][HID];    // 32 KB
    __shared__ float xs[32][INC];     // 16 KB
    int tx = threadIdx.x, ty = threadIdx.y;          // blockDim (16,16)
    int tid = ty * 16 + tx;
    for (int i = tid; i < INC * HID; i += 256)
        ((float*)Ws)[i] = W[i];
    int row0 = blockIdx.x * 32;
    for (int i = tid; i < 32 * INC; i += 256) {
        int r = i >> 7, k = i & 127;
        int row = row0 + r;
        xs[r][k] = (row < n) ? x[row * INC + k] : 0.f;
    }
    __syncthreads();

    float4 a0 = make_float4(0.f, 0.f, 0.f, 0.f);
    float4 a1 = make_float4(0.f, 0.f, 0.f, 0.f);
    #pragma unroll 4
    for (int k = 0; k < INC; k++) {
        float4 w = *(const float4*)&Ws[k][tx * 4];
        float v0 = xs[ty][k];
        float v1 = xs[ty + 16][k];
        a0.x += v0 * w.x; a0.y += v0 * w.y; a0.z += v0 * w.z; a0.w += v0 * w.w;
        a1.x += v1 * w.x; a1.y += v1 * w.y; a1.z += v1 * w.z; a1.w += v1 * w.w;
    }
    int r0 = row0 + ty, r1 = row0 + ty + 16;
    if (r0 < n) {
        g_h0h[r0 * 32 + tx * 2]     = __floats2half2_rn(a0.x, a0.y);
        g_h0h[r0 * 32 + tx * 2 + 1] = __floats2half2_rn(a0.z, a0.w);
    }
    if (r1 < n) {
        g_h0h[r1 * 32 + tx * 2]     = __floats2half2_rn(a1.x, a1.y);
        g_h0h[r1 * 32 + tx * 2 + 1] = __floats2half2_rn(a1.z, a1.w);
    }
}

// ---------------- kernel 4: fused layer-1 aggregation + GEMM2 ----------------
// One warp per node; per-edge dis[src] weight (warp-uniform broadcast load).
__global__ __launch_bounds__(256) void k_agg64_gemm2(const float* __restrict__ b1,
                                                     const float* __restrict__ Wmu,
                                                     const float* __restrict__ Wls,
                                                     int n) {
    __shared__ float hs[8][HID];     // 2 KB
    __shared__ float Wc[HID][32];    // 8 KB
    int tid  = threadIdx.x;
    int warp = tid >> 5, lane = tid & 31;
    for (int i = tid; i < HID * OUTC; i += 256) {
        int k = i >> 4, c = i & 15;
        Wc[k][c]      = Wmu[i];
        Wc[k][16 + c] = Wls[i];
    }
    int node = blockIdx.x * 8 + warp;
    float dnode = 0.f;
    if (node < n) {
        dnode = g_dis[node];
        float2 self = __half22float2(g_h0h[node * 32 + lane]);
        float2 acc;
        acc.x = self.x * dnode;                  // self-loop term dis[d]*h0[d]
        acc.y = self.y * dnode;
        int k   = g_off[node];
        int end = g_off[node + 1];
        while (k < end && (k & 3)) {
            int s0 = g_csr[k];
            float w0 = g_dis[s0];
            float2 a0 = __half22float2(g_h0h[s0 * 32 + lane]);
            acc.x += w0 * a0.x; acc.y += w0 * a0.y;
            k++;
        }
        for (; k + 7 < end; k += 8) {
            int4 i0 = *(const int4*)&g_csr[k];
            int4 i1 = *(const int4*)&g_csr[k + 4];
            float w0 = g_dis[i0.x], w1 = g_dis[i0.y];
            float w2 = g_dis[i0.z], w3 = g_dis[i0.w];
            float w4 = g_dis[i1.x], w5 = g_dis[i1.y];
            float w6 = g_dis[i1.z], w7 = g_dis[i1.w];
            float2 a0 = __half22float2(g_h0h[i0.x * 32 + lane]);
            float2 a1 = __half22float2(g_h0h[i0.y * 32 + lane]);
            float2 a2 = __half22float2(g_h0h[i0.z * 32 + lane]);
            float2 a3 = __half22float2(g_h0h[i0.w * 32 + lane]);
            float2 a4 = __half22float2(g_h0h[i1.x * 32 + lane]);
            float2 a5 = __half22float2(g_h0h[i1.y * 32 + lane]);
            float2 a6 = __half22float2(g_h0h[i1.z * 32 + lane]);
            float2 a7 = __half22float2(g_h0h[i1.w * 32 + lane]);
            acc.x += (w0*a0.x + w1*a1.x) + (w2*a2.x + w3*a3.x)
                   + ((w4*a4.x + w5*a5.x) + (w6*a6.x + w7*a7.x));
            acc.y += (w0*a0.y + w1*a1.y) + (w2*a2.y + w3*a3.y)
                   + ((w4*a4.y + w5*a5.y) + (w6*a6.y + w7*a7.y));
        }
        if (k + 3 < end) {
            int4 i0 = *(const int4*)&g_csr[k];
            float w0 = g_dis[i0.x], w1 = g_dis[i0.y];
            float w2 = g_dis[i0.z], w3 = g_dis[i0.w];
            float2 a0 = __half22float2(g_h0h[i0.x * 32 + lane]);
            float2 a1 = __half22float2(g_h0h[i0.y * 32 + lane]);
            float2 a2 = __half22float2(g_h0h[i0.z * 32 + lane]);
            float2 a3 = __half22float2(g_h0h[i0.w * 32 + lane]);
            acc.x += (w0*a0.x + w1*a1.x) + (w2*a2.x + w3*a3.x);
            acc.y += (w0*a0.y + w1*a1.y) + (w2*a2.y + w3*a3.y);
            k += 4;
        }
        for (; k < end; k++) {
            int s0 = g_csr[k];
            float w0 = g_dis[s0];
            float2 a0 = __half22float2(g_h0h[s0 * 32 + lane]);
            acc.x += w0 * a0.x; acc.y += w0 * a0.y;
        }
        int c2 = lane * 2;
        float2 bb = *(const float2*)&b1[c2];
        hs[warp][c2]     = fmaxf(acc.x * dnode + bb.x, 0.f);
        hs[warp][c2 + 1] = fmaxf(acc.y * dnode + bb.y, 0.f);
    }
    __syncthreads();
    if (node < n) {
        float s0 = 0.f, s1 = 0.f;
        #pragma unroll
        for (int k = 0; k < HID; k++) {
            float hv = hs[warp][k];
            s0 += hv * Wc[k][(lane & 15) * 2];
            s1 += hv * Wc[k][(lane & 15) * 2 + 1];
        }
        if (lane < 16)
            g_zh[node * 16 + lane] = __floats2half2_rn(s0, s1);   // UNSCALED
    }
}

// ---------------- kernel 5: layer-2 aggregation (16-lane subwarp/node) -------
__global__ __launch_bounds__(256) void k_agg32(const float* __restrict__ bmu,
                                               const float* __restrict__ bls,
                                               float* __restrict__ out, int n) {
    int tid  = threadIdx.x;
    int node = blockIdx.x * 16 + (tid >> 4);
    if (node >= n) return;
    int li = tid & 15;
    float dnode = g_dis[node];
    float2 self = __half22float2(g_zh[node * 16 + li]);
    float2 acc;
    acc.x = self.x * dnode;
    acc.y = self.y * dnode;
    int k   = g_off[node];
    int end = g_off[node + 1];
    while (k < end && (k & 3)) {
        int s0 = g_csr[k];
        float w0 = g_dis[s0];
        float2 a0 = __half22float2(g_zh[s0 * 16 + li]);
        acc.x += w0 * a0.x; acc.y += w0 * a0.y;
        k++;
    }
    for (; k + 7 < end; k += 8) {
        int4 i0 = *(const int4*)&g_csr[k];
        int4 i1 = *(const int4*)&g_csr[k + 4];
        float w0 = g_dis[i0.x], w1 = g_dis[i0.y];
        float w2 = g_dis[i0.z], w3 = g_dis[i0.w];
        float w4 = g_dis[i1.x], w5 = g_dis[i1.y];
        float w6 = g_dis[i1.z], w7 = g_dis[i1.w];
        float2 a0 = __half22float2(g_zh[i0.x * 16 + li]);
        float2 a1 = __half22float2(g_zh[i0.y * 16 + li]);
        float2 a2 = __half22float2(g_zh[i0.z * 16 + li]);
        float2 a3 = __half22float2(g_zh[i0.w * 16 + li]);
        float2 a4 = __half22float2(g_zh[i1.x * 16 + li]);
        float2 a5 = __half22float2(g_zh[i1.y * 16 + li]);
        float2 a6 = __half22float2(g_zh[i1.z * 16 + li]);
        float2 a7 = __half22float2(g_zh[i1.w * 16 + li]);
        acc.x += (w0*a0.x + w1*a1.x) + (w2*a2.x + w3*a3.x)
               + ((w4*a4.x + w5*a5.x) + (w6*a6.x + w7*a7.x));
        acc.y += (w0*a0.y + w1*a1.y) + (w2*a2.y + w3*a3.y)
               + ((w4*a4.y + w5*a5.y) + (w6*a6.y + w7*a7.y));
    }
    if (k + 3 < end) {
        int4 i0 = *(const int4*)&g_csr[k];
        float w0 = g_dis[i0.x], w1 = g_dis[i0.y];
        float w2 = g_dis[i0.z], w3 = g_dis[i0.w];
        float2 a0 = __half22float2(g_zh[i0.x * 16 + li]);
        float2 a1 = __half22float2(g_zh[i0.y * 16 + li]);
        float2 a2 = __half22float2(g_zh[i0.z * 16 + li]);
        float2 a3 = __half22float2(g_zh[i0.w * 16 + li]);
        acc.x += (w0*a0.x + w1*a1.x) + (w2*a2.x + w3*a3.x);
        acc.y += (w0*a0.y + w1*a1.y) + (w2*a2.y + w3*a3.y);
        k += 4;
    }
    for (; k < end; k++) {
        int s0 = g_csr[k];
        float w0 = g_dis[s0];
        float2 a0 = __half22float2(g_zh[s0 * 16 + li]);
        acc.x += w0 * a0.x; acc.y += w0 * a0.y;
    }
    int c2 = li * 2;
    float2 r;
    if (c2 < 16) {
        const float2 bb = *(const float2*)&bmu[c2];
        r.x = acc.x * dnode + bb.x; r.y = acc.y * dnode + bb.y;
        *(float2*)&out[node * 16 + c2] = r;
    } else {
        const float2 bb = *(const float2*)&bls[c2 - 16];
        r.x = acc.x * dnode + bb.x; r.y = acc.y * dnode + bb.y;
        *(float2*)&out[n * 16 + node * 16 + (c2 - 16)] = r;
    }
}

// ---------------- launch ------------------------------------------------------
extern "C" void kernel_launch(void* const* d_in, const int* in_sizes, int n_in,
                              void* d_out, int out_size) {
    const float* x   = (const float*)d_in[0];
    const void*  eix = d_in[1];
    const float* W1  = (const float*)d_in[2];
    const float* b1  = (const float*)d_in[3];
    const float* Wmu = (const float*)d_in[4];
    const float* bmu = (const float*)d_in[5];
    const float* Wls = (const float*)d_in[6];
    const float* bls = (const float*)d_in[7];
    float* out = (float*)d_out;

    int n = in_sizes[0] / INC;      // 100000
    int E = in_sizes[1] / 2;        // 3200000
    int nb = (n + 255) / 256;       // 391

    // launch 1 (s2): gemm1f depends only on x, W1
    cudaEventRecord(g_res.ev_fork, 0);
    cudaStreamWaitEvent(g_res.s2, g_res.ev_fork, 0);
    k_gemm1f<<<(n + 31) / 32, dim3(16, 16), 0, g_res.s2>>>(x, W1, n);
    cudaEventRecord(g_res.ev_join, g_res.s2);

    // launch 2: degree count (g_degi is zero at entry by invariant)
    k_conv_count<<<(E + 255) / 256, 256>>>(eix, E);

    // launch 3: cooperative scan + dis + scatter
    {
        void* args[] = { (void*)&eix, (void*)&n, (void*)&E, (void*)&nb };
        cudaLaunchCooperativeKernel((void*)k_coop, dim3(592), dim3(256), args, 0, (cudaStream_t)0);
    }

    // launch 4: fused agg + projection (needs h0h from s2)
    cudaStreamWaitEvent(0, g_res.ev_join, 0);
    k_agg64_gemm2<<<(n + 7) / 8, 256>>>(b1, Wmu, Wls, n);

    // launch 5: final aggregation
    k_agg32<<<(n + 15) / 16, 256>>>(bmu, bls, out, n);
}